// round 17
// baseline (speedup 1.0000x reference)
#include <cuda_runtime.h>
#include <cstdint>
#include <math.h>

// ---------------------------------------------------------------------------
// Qwen3 attention block. Round 17: GEMM at 512 threads / 16 warps, SAME tile
// (128x256) — isolates warp-count axis at constant tile/traffic/ratio.
// Warp tile 32x64 (4M x 4N warps), 64 accumulators/thread, regs capped 128.
// Flash cp.async+LPT (R16), fused norm epilogue (R14), side-stream w_o kept.
// ---------------------------------------------------------------------------

#define T_SEQ 2048
#define HID   4096
#define NQH   32
#define NKV   8
#define HD    128
#define QKV_N 6144
#define O_N   4096

__device__ float g_qkv[(size_t)T_SEQ * QKV_N];
__device__ float g_attn[(size_t)T_SEQ * O_N];
__device__ float g_hidr[(size_t)T_SEQ * HID];
__device__ float g_wqkvr[(size_t)HID * QKV_N];
__device__ float g_wor[(size_t)HID * O_N];

__device__ __forceinline__ float f2tf32(float x) {
    uint32_t u;
    asm("cvt.rna.tf32.f32 %0, %1;" : "=r"(u) : "f"(x));
    return __uint_as_float(u);
}

__device__ __forceinline__ void mma8(float& c0, float& c1, float& c2, float& c3,
                                     float a0, float a1, float a2, float a3,
                                     float b0, float b1) {
    asm volatile(
        "mma.sync.aligned.m16n8k8.row.col.f32.tf32.tf32.f32 "
        "{%0,%1,%2,%3}, {%4,%5,%6,%7}, {%8,%9}, {%0,%1,%2,%3};\n"
        : "+f"(c0), "+f"(c1), "+f"(c2), "+f"(c3)
        : "r"(__float_as_uint(a0)), "r"(__float_as_uint(a1)),
          "r"(__float_as_uint(a2)), "r"(__float_as_uint(a3)),
          "r"(__float_as_uint(b0)), "r"(__float_as_uint(b1)));
}

__device__ __forceinline__ uint32_t s2u(const void* p) {
    return (uint32_t)__cvta_generic_to_shared(p);
}
#define CPASYNC16(dst_u32, src_ptr) \
    asm volatile("cp.async.cg.shared.global [%0], [%1], 16;\n" \
                 :: "r"(dst_u32), "l"(src_ptr))

// ---------------------------------------------------------------------------
// Pipelined GEMM: C[M,N] = A[M,K] @ B[K,N], tf32 operands.
// Block 128x256, BK=32, 512 threads = 16 warps (4M x 4N, warp tile 32x64).
// 4-stage cp.async ring, one __syncthreads per k-iter (R10 schedule).
// fuse=1: RMSNorm+RoPE epilogue; K/V regions stored tf32-rounded.
// ---------------------------------------------------------------------------
#define BM 128
#define BN 256
#define BK 32
#define ASTRD 36
#define BSTRD 264
#define STG_FLOATS (BM * ASTRD + BK * BSTRD)            // 13056
#define GEMM_SMEM (4 * STG_FLOATS * 4)                  // 208896 B
#define CSTRD 264

__global__ __launch_bounds__(512, 1)
void gemm_tf32_pipe(const float* __restrict__ A, const float* __restrict__ B,
                    float* __restrict__ C, int M, int N, int K,
                    const float* __restrict__ qw, const float* __restrict__ kw,
                    int fuse) {
    extern __shared__ float sm[];

    const int tid  = threadIdx.x;
    const int warp = tid >> 5, lane = tid & 31;
    const int tq = lane >> 2, tr = lane & 3;
    const int wm = (warp & 3) * 32;
    const int wn = (warp >> 2) * 64;
    const size_t bm = (size_t)blockIdx.x * BM;
    const size_t bn = (size_t)blockIdx.y * BN;

    float c[2][8][4];
    #pragma unroll
    for (int mi = 0; mi < 2; mi++)
        #pragma unroll
        for (int ni = 0; ni < 8; ni++)
            #pragma unroll
            for (int e = 0; e < 4; e++) c[mi][ni][e] = 0.f;

    const int NT = K / BK;

    // staging: A 128x32 = 1024 float4 (2/thr), B 32x256 = 2048 float4 (4/thr)
    auto stage = [&](int kt, int s) {
        float* sa = sm + s * STG_FLOATS;
        float* sb = sa + BM * ASTRD;
        #pragma unroll
        for (int i = 0; i < 2; i++) {
            int cdx = tid + 512 * i;
            int row = cdx >> 3, c4 = (cdx & 7) * 4;
            CPASYNC16(s2u(sa + row * ASTRD + c4),
                      A + (bm + row) * (size_t)K + kt + c4);
        }
        #pragma unroll
        for (int i = 0; i < 4; i++) {
            int cdx = tid + 512 * i;
            int row = cdx >> 6, c4 = (cdx & 63) * 4;
            CPASYNC16(s2u(sb + row * BSTRD + c4),
                      B + (size_t)(kt + row) * N + bn + c4);
        }
        asm volatile("cp.async.commit_group;\n");
    };

    stage(0, 0);
    stage(BK, 1);

    for (int t = 0; t < NT; t++) {
        if (t + 2 < NT) {
            stage((t + 2) * BK, (t + 2) & 3);
            asm volatile("cp.async.wait_group 2;\n");
        } else if (t + 1 < NT) {
            asm volatile("cp.async.wait_group 1;\n");
        } else {
            asm volatile("cp.async.wait_group 0;\n");
        }
        __syncthreads();

        const float* sa = sm + (t & 3) * STG_FLOATS;
        const float* sb = sa + BM * ASTRD;

        #pragma unroll
        for (int kk = 0; kk < 4; kk++) {
            const int k0 = 8 * kk + tr;
            float a[2][4];
            #pragma unroll
            for (int mi = 0; mi < 2; mi++) {
                const int r0 = wm + 16 * mi + tq;
                a[mi][0] = sa[r0 * ASTRD + k0];
                a[mi][1] = sa[(r0 + 8) * ASTRD + k0];
                a[mi][2] = sa[r0 * ASTRD + k0 + 4];
                a[mi][3] = sa[(r0 + 8) * ASTRD + k0 + 4];
            }
            float b[8][2];
            #pragma unroll
            for (int ni = 0; ni < 8; ni++) {
                const int col = wn + 8 * ni + tq;
                b[ni][0] = sb[k0 * BSTRD + col];
                b[ni][1] = sb[(k0 + 4) * BSTRD + col];
            }
            #pragma unroll
            for (int mi = 0; mi < 2; mi++)
                #pragma unroll
                for (int ni = 0; ni < 8; ni++)
                    mma8(c[mi][ni][0], c[mi][ni][1], c[mi][ni][2], c[mi][ni][3],
                         a[mi][0], a[mi][1], a[mi][2], a[mi][3],
                         b[ni][0], b[ni][1]);
        }
    }

    if (!fuse) {
        #pragma unroll
        for (int mi = 0; mi < 2; mi++) {
            #pragma unroll
            for (int ni = 0; ni < 8; ni++) {
                size_t r  = bm + wm + 16 * mi + tq;
                size_t cc = bn + wn + 8 * ni + 2 * tr;
                *(float2*)(C + r * N + cc)       = make_float2(c[mi][ni][0], c[mi][ni][1]);
                *(float2*)(C + (r + 8) * N + cc) = make_float2(c[mi][ni][2], c[mi][ni][3]);
            }
        }
        return;
    }

    // ---- fused epilogue: RMSNorm+RoPE; K/V stored tf32-rounded ----
    __syncthreads();
    float (*Cs)[CSTRD] = (float(*)[CSTRD])sm;
    #pragma unroll
    for (int mi = 0; mi < 2; mi++) {
        #pragma unroll
        for (int ni = 0; ni < 8; ni++) {
            int r  = wm + 16 * mi + tq;
            int cc = wn + 8 * ni + 2 * tr;
            *(float2*)&Cs[r][cc]     = make_float2(c[mi][ni][0], c[mi][ni][1]);
            *(float2*)&Cs[r + 8][cc] = make_float2(c[mi][ni][2], c[mi][ni][3]);
        }
    }
    __syncthreads();

    const int gh0 = (int)(bn >> 7);
    for (int it = 0; it < 16; it++) {
        const int p   = warp * 16 + it;        // pair id 0..255
        const int row = p & 127;
        const int hl  = p >> 7;
        const int gh  = gh0 + hl;
        const float* src = &Cs[row][hl * HD];
        float* dst = C + (bm + row) * (size_t)N + bn + hl * HD;

        float v0 = src[lane];
        float v1 = src[lane + 32];
        float v2 = src[lane + 64];
        float v3 = src[lane + 96];

        if (gh >= NQH + NKV) {
            dst[lane]      = f2tf32(v0);
            dst[lane + 32] = f2tf32(v1);
            dst[lane + 64] = f2tf32(v2);
            dst[lane + 96] = f2tf32(v3);
        } else {
            float ss = v0 * v0 + v1 * v1 + v2 * v2 + v3 * v3;
            #pragma unroll
            for (int o = 16; o > 0; o >>= 1) ss += __shfl_xor_sync(0xffffffffu, ss, o);
            float scale = rsqrtf(ss * (1.0f / HD) + 1e-6f);
            const float* wv = (gh < NQH) ? qw : kw;
            float x1a = v0 * scale * wv[lane];
            float x2a = v2 * scale * wv[lane + 64];
            float x1b = v1 * scale * wv[lane + 32];
            float x2b = v3 * scale * wv[lane + 96];
            float tpos = (float)(bm + row);
            float ia = exp2f(-(float)lane        * (19.931568569324174f / 64.0f));
            float ib = exp2f(-(float)(lane + 32) * (19.931568569324174f / 64.0f));
            float sa_, ca_, sb_, cb_;
            sincosf(tpos * ia, &sa_, &ca_);
            sincosf(tpos * ib, &sb_, &cb_);
            float o0 = x1a * ca_ - x2a * sa_;
            float o2 = x2a * ca_ + x1a * sa_;
            float o1 = x1b * cb_ - x2b * sb_;
            float o3 = x2b * cb_ + x1b * sb_;
            if (gh >= NQH) {
                o0 = f2tf32(o0); o1 = f2tf32(o1);
                o2 = f2tf32(o2); o3 = f2tf32(o3);
            }
            dst[lane]      = o0;
            dst[lane + 64] = o2;
            dst[lane + 32] = o1;
            dst[lane + 96] = o3;
        }
    }
}

// ---------------------------------------------------------------------------
// prepass: elementwise tf32 rounding
// ---------------------------------------------------------------------------
__global__ void round_copy(const float* __restrict__ src, float* __restrict__ dst,
                           int n4) {
    int i = blockIdx.x * blockDim.x + threadIdx.x;
    if (i < n4) {
        float4 v = ((const float4*)src)[i];
        v.x = f2tf32(v.x); v.y = f2tf32(v.y); v.z = f2tf32(v.z); v.w = f2tf32(v.w);
        ((float4*)dst)[i] = v;
    }
}

// ---------------------------------------------------------------------------
// GQA flash attention, cp.async double-buffered KV, LPT order (R16).
// ---------------------------------------------------------------------------
#define QSTR 132
#define KSTR 132
#define VSTR 136
#define PSTR 68
#define PS_FLOATS   (128 * PSTR)
#define KV_FLOATS   (64 * KSTR + 64 * VSTR)
#define ATTN_SMEM   ((PS_FLOATS + 2 * KV_FLOATS) * 4)

__global__ __launch_bounds__(256, 1)
void flash_attn() {
    extern __shared__ float sm[];
    float (*Ps)[PSTR] = (float(*)[PSTR])sm;
    float* kv0 = sm + PS_FLOATS;
    float* kv1 = sm + PS_FLOATS + KV_FLOATS;
    float* Qsp = kv1;

    const int kh = blockIdx.x;
    const int qb = (T_SEQ / 32 - 1) - blockIdx.y;
    const int tid = threadIdx.x;
    const int w = tid >> 5, lane = tid & 31;
    const int tq = lane >> 2, tr = lane & 3;
    const int hl = w >> 1;
    const int h  = 4 * kh + hl;
    const int wrow = (w & 1) * 16;
    const float scaling = 0.08838834764831845f;
    const int kb_last = (32 * qb + 31) >> 6;

    auto stage_kv = [&](int kb, float* buf) {
        float* Kb = buf;
        float* Vb = buf + 64 * KSTR;
        #pragma unroll
        for (int i = 0; i < 8; i++) {
            int f = tid + 256 * i;
            int row = f >> 5, c4 = (f & 31) * 4;
            const float* rp = g_qkv + (size_t)(64 * kb + row) * QKV_N + kh * HD + c4;
            CPASYNC16(s2u(Kb + row * KSTR + c4), rp + 4096);
            CPASYNC16(s2u(Vb + row * VSTR + c4), rp + 5120);
        }
        asm volatile("cp.async.commit_group;\n");
    };

    stage_kv(0, kv0);
    #pragma unroll
    for (int i = 0; i < 16; i++) {
        int f = tid + 256 * i;
        int head = f >> 10;
        int row  = (f >> 5) & 31;
        int c4   = (f & 31) * 4;
        float4 v = *(const float4*)(g_qkv + (size_t)(32 * qb + row) * QKV_N
                                    + (4 * kh + head) * HD + c4);
        v.x = f2tf32(v.x * scaling); v.y = f2tf32(v.y * scaling);
        v.z = f2tf32(v.z * scaling); v.w = f2tf32(v.w * scaling);
        *(float4*)&Qsp[head * 32 * QSTR + row * QSTR + c4] = v;
    }
    __syncthreads();

    float qf[16][4];
    const float* qbase = Qsp + hl * 32 * QSTR;
    #pragma unroll
    for (int kk = 0; kk < 16; kk++) {
        int r0 = wrow + tq, k0 = 8 * kk + tr;
        qf[kk][0] = qbase[r0 * QSTR + k0];
        qf[kk][1] = qbase[(r0 + 8) * QSTR + k0];
        qf[kk][2] = qbase[r0 * QSTR + k0 + 4];
        qf[kk][3] = qbase[(r0 + 8) * QSTR + k0 + 4];
    }
    asm volatile("cp.async.wait_group 0;\n");
    __syncthreads();

    float o[16][4];
    #pragma unroll
    for (int ni = 0; ni < 16; ni++)
        #pragma unroll
        for (int e = 0; e < 4; e++) o[ni][e] = 0.f;
    float m1 = -1e30f, m2 = -1e30f, l1 = 0.f, l2 = 0.f;

    const int r1 = 16 * w + tq, r2 = r1 + 8;
    const int rowg1 = 32 * qb + wrow + tq;
    const int rowg2 = rowg1 + 8;

    for (int kb = 0; kb <= kb_last; kb++) {
        if (kb > 0) {
            asm volatile("cp.async.wait_group 0;\n");
            __syncthreads();
        }
        if (kb + 1 <= kb_last)
            stage_kv(kb + 1, ((kb + 1) & 1) ? kv1 : kv0);

        const float* Kb = (kb & 1) ? kv1 : kv0;
        const float* Vb = Kb + 64 * KSTR;

        float s[8][4];
        #pragma unroll
        for (int ni = 0; ni < 8; ni++)
            #pragma unroll
            for (int e = 0; e < 4; e++) s[ni][e] = 0.f;

        #pragma unroll
        for (int kk = 0; kk < 16; kk++) {
            const int d0 = 8 * kk + tr;
            #pragma unroll
            for (int ni = 0; ni < 8; ni++) {
                float b0 = Kb[(8 * ni + tq) * KSTR + d0];
                float b1 = Kb[(8 * ni + tq) * KSTR + d0 + 4];
                mma8(s[ni][0], s[ni][1], s[ni][2], s[ni][3],
                     qf[kk][0], qf[kk][1], qf[kk][2], qf[kk][3], b0, b1);
            }
        }

        if (kb == kb_last) {
            #pragma unroll
            for (int ni = 0; ni < 8; ni++) {
                int c0g = 64 * kb + 8 * ni + 2 * tr;
                if (c0g     > rowg1) s[ni][0] = -1e30f;
                if (c0g + 1 > rowg1) s[ni][1] = -1e30f;
                if (c0g     > rowg2) s[ni][2] = -1e30f;
                if (c0g + 1 > rowg2) s[ni][3] = -1e30f;
            }
        }

        float tm1 = -1e30f, tm2 = -1e30f;
        #pragma unroll
        for (int ni = 0; ni < 8; ni++) {
            tm1 = fmaxf(tm1, fmaxf(s[ni][0], s[ni][1]));
            tm2 = fmaxf(tm2, fmaxf(s[ni][2], s[ni][3]));
        }
        tm1 = fmaxf(tm1, __shfl_xor_sync(0xffffffffu, tm1, 1));
        tm1 = fmaxf(tm1, __shfl_xor_sync(0xffffffffu, tm1, 2));
        tm2 = fmaxf(tm2, __shfl_xor_sync(0xffffffffu, tm2, 1));
        tm2 = fmaxf(tm2, __shfl_xor_sync(0xffffffffu, tm2, 2));

        float nm1 = fmaxf(m1, tm1), nm2 = fmaxf(m2, tm2);
        float a1 = __expf(m1 - nm1), a2 = __expf(m2 - nm2);

        float rs1 = 0.f, rs2 = 0.f;
        #pragma unroll
        for (int ni = 0; ni < 8; ni++) {
            int c0 = 8 * ni + 2 * tr;
            float p0 = __expf(s[ni][0] - nm1);
            float p1 = __expf(s[ni][1] - nm1);
            float p2 = __expf(s[ni][2] - nm2);
            float p3 = __expf(s[ni][3] - nm2);
            rs1 += p0 + p1; rs2 += p2 + p3;
            Ps[r1][c0]     = f2tf32(p0);
            Ps[r1][c0 + 1] = f2tf32(p1);
            Ps[r2][c0]     = f2tf32(p2);
            Ps[r2][c0 + 1] = f2tf32(p3);
        }
        rs1 += __shfl_xor_sync(0xffffffffu, rs1, 1);
        rs1 += __shfl_xor_sync(0xffffffffu, rs1, 2);
        rs2 += __shfl_xor_sync(0xffffffffu, rs2, 1);
        rs2 += __shfl_xor_sync(0xffffffffu, rs2, 2);

        l1 = l1 * a1 + rs1; l2 = l2 * a2 + rs2;
        m1 = nm1; m2 = nm2;

        #pragma unroll
        for (int ni = 0; ni < 16; ni++) {
            o[ni][0] *= a1; o[ni][1] *= a1;
            o[ni][2] *= a2; o[ni][3] *= a2;
        }

        __syncwarp();

        #pragma unroll
        for (int kp = 0; kp < 8; kp++) {
            float a0  = Ps[r1][8 * kp + tr];
            float a1f = Ps[r2][8 * kp + tr];
            float a2f = Ps[r1][8 * kp + tr + 4];
            float a3f = Ps[r2][8 * kp + tr + 4];
            #pragma unroll
            for (int ni = 0; ni < 16; ni++) {
                float b0 = Vb[(8 * kp + tr) * VSTR + 8 * ni + tq];
                float b1 = Vb[(8 * kp + tr + 4) * VSTR + 8 * ni + tq];
                mma8(o[ni][0], o[ni][1], o[ni][2], o[ni][3], a0, a1f, a2f, a3f, b0, b1);
            }
        }
    }

    const float inv1 = 1.0f / l1, inv2 = 1.0f / l2;
    #pragma unroll
    for (int ni = 0; ni < 16; ni++) {
        int d = 8 * ni + 2 * tr;
        *(float2*)(g_attn + (size_t)rowg1 * O_N + h * HD + d) =
            make_float2(f2tf32(o[ni][0] * inv1), f2tf32(o[ni][1] * inv1));
        *(float2*)(g_attn + (size_t)rowg2 * O_N + h * HD + d) =
            make_float2(f2tf32(o[ni][2] * inv2), f2tf32(o[ni][3] * inv2));
    }
}

// ---------------------------------------------------------------------------
extern "C" void kernel_launch(void* const* d_in, const int* in_sizes, int n_in,
                              void* d_out, int out_size) {
    const float* hidden = (const float*)d_in[1];
    const float* w_qkv  = (const float*)d_in[2];
    const float* qw     = (const float*)d_in[3];
    const float* kw     = (const float*)d_in[4];
    const float* w_o    = (const float*)d_in[5];
    float* out = (float*)d_out;

    void *qkv_p = nullptr, *attn_p = nullptr, *hidr_p = nullptr;
    void *wqkvr_p = nullptr, *wor_p = nullptr;
    cudaGetSymbolAddress(&qkv_p, g_qkv);
    cudaGetSymbolAddress(&attn_p, g_attn);
    cudaGetSymbolAddress(&hidr_p, g_hidr);
    cudaGetSymbolAddress(&wqkvr_p, g_wqkvr);
    cudaGetSymbolAddress(&wor_p, g_wor);

    static bool init_done = false;
    static cudaStream_t s_side = nullptr;
    static cudaEvent_t ev_fork = nullptr, ev_join = nullptr;
    if (!init_done) {
        cudaFuncSetAttribute(gemm_tf32_pipe,
                             cudaFuncAttributeMaxDynamicSharedMemorySize, GEMM_SMEM);
        cudaFuncSetAttribute(flash_attn,
                             cudaFuncAttributeMaxDynamicSharedMemorySize, ATTN_SMEM);
        cudaStreamCreateWithFlags(&s_side, cudaStreamNonBlocking);
        cudaEventCreateWithFlags(&ev_fork, cudaEventDisableTiming);
        cudaEventCreateWithFlags(&ev_join, cudaEventDisableTiming);
        init_done = true;
    }

    round_copy<<<(T_SEQ * HID / 4 + 255) / 256, 256>>>(
        hidden, (float*)hidr_p, T_SEQ * HID / 4);

    cudaEventRecord(ev_fork, 0);
    cudaStreamWaitEvent(s_side, ev_fork, 0);
    round_copy<<<(HID * O_N / 4 + 255) / 256, 256, 0, s_side>>>(
        w_o, (float*)wor_p, HID * O_N / 4);
    cudaEventRecord(ev_join, s_side);

    round_copy<<<(HID * QKV_N / 4 + 255) / 256, 256>>>(
        w_qkv, (float*)wqkvr_p, HID * QKV_N / 4);

    gemm_tf32_pipe<<<dim3(T_SEQ / BM, QKV_N / BN), 512, GEMM_SMEM>>>(
        (const float*)hidr_p, (const float*)wqkvr_p, (float*)qkv_p,
        T_SEQ, QKV_N, HID, qw, kw, 1);

    flash_attn<<<dim3(NKV, T_SEQ / 32), 256, ATTN_SMEM>>>();

    cudaStreamWaitEvent(0, ev_join, 0);

    gemm_tf32_pipe<<<dim3(T_SEQ / BM, O_N / BN), 512, GEMM_SMEM>>>(
        (const float*)attn_p, (const float*)wor_p, out,
        T_SEQ, O_N, HID, nullptr, nullptr, 0);
}